// round 5
// baseline (speedup 1.0000x reference)
#include <cuda_runtime.h>

// Problem constants (fixed shapes from reference setup_inputs)
#define NN    16384          // nodes
#define FIN   512            // input features
#define NH    4              // heads
#define C1    128            // layer-1 per-head channels
#define LATD  64             // layer-2 per-head channels
#define ERAW  262144         // raw edges
#define ETOT  (ERAW + NN)    // + self loops = 278528
#define F1    (NH * C1)      // 512
#define F2    (NH * LATD)    // 256

// ---------------- static scratch (device globals; no runtime alloc) --------
__device__ __align__(16) float g_h1  [(size_t)NN * F1];   // layer-1 projection  (32 MB)
__device__ __align__(16) float g_out1[(size_t)NN * F1];   // layer-1 output      (32 MB)
__device__ __align__(16) float g_h2  [(size_t)NN * F2];   // layer-2 projection  (16 MB)
__device__ float g_als1[NN * NH];
__device__ float g_ald1[NN * NH];
__device__ float g_als2[NN * NH];
__device__ float g_ald2[NN * NH];
__device__ int   g_rowptr[NN + 1];
__device__ int   g_col[ETOT];
__device__ int   g_deg[NN];
__device__ int   g_fill[NN];
__device__ int   g_is64;     // edge_index dtype flag (1 = int64, 0 = int32)

// ---------------- edge dtype detection -------------------------------------
// int32 data viewed as int64 packs two (almost surely nonzero) node ids into
// one value >= 2^32 -> out of [0, NN). Genuine int64 ids are all in range.
__global__ void k_detect(const void* __restrict__ ei) {
    if (threadIdx.x == 0 && blockIdx.x == 0) {
        const long long* p = (const long long*)ei;
        int ok = 1;
        for (int i = 0; i < 64; i++) {
            long long v = p[i];
            if (v < 0 || v >= NN) ok = 0;
        }
        g_is64 = ok;
    }
}

__device__ __forceinline__ int edge_at(const void* ei, int idx) {
    if (g_is64) return (int)((const long long*)ei)[idx];
    return ((const int*)ei)[idx];
}

// ---------------- CSR build over dst ---------------------------------------
__global__ void k_init_deg() {
    int i = blockIdx.x * blockDim.x + threadIdx.x;
    if (i < NN) g_deg[i] = 1;                    // self loop
}

__global__ void k_count_deg(const void* __restrict__ ei) {
    int e = blockIdx.x * blockDim.x + threadIdx.x;
    if (e < ERAW) atomicAdd(&g_deg[edge_at(ei, ERAW + e)], 1);
}

// single-block exclusive scan over 16384 degrees (1024 thr x 16 each)
__global__ void k_scan() {
    __shared__ int part[1024];
    int t = threadIdx.x;
    int base = t * 16;
    int loc[16];
    int s = 0;
#pragma unroll
    for (int i = 0; i < 16; i++) { loc[i] = s; s += g_deg[base + i]; }
    part[t] = s;
    __syncthreads();
    for (int off = 1; off < 1024; off <<= 1) {
        int v = (t >= off) ? part[t - off] : 0;
        __syncthreads();
        part[t] += v;
        __syncthreads();
    }
    int pre = (t == 0) ? 0 : part[t - 1];
#pragma unroll
    for (int i = 0; i < 16; i++) g_rowptr[base + i] = pre + loc[i];
    if (t == 1023) g_rowptr[NN] = part[1023];
}

__global__ void k_selfloop() {
    int i = blockIdx.x * blockDim.x + threadIdx.x;
    if (i < NN) { g_col[g_rowptr[i]] = i; g_fill[i] = 1; }
}

__global__ void k_scatter(const void* __restrict__ ei) {
    int e = blockIdx.x * blockDim.x + threadIdx.x;
    if (e < ERAW) {
        int d = edge_at(ei, ERAW + e);
        int pos = g_rowptr[d] + atomicAdd(&g_fill[d], 1);
        g_col[pos] = edge_at(ei, e);
    }
}

// ---------------- fp32 SGEMM: C[M,N] = A[M,K] * B[K,N] (all row-major) -----
// BM=BN=128, BK=8, 256 threads, 8x8 per-thread micro-tile.
// LAYER 0: A = x (param),      B = W1 (param), C = g_h1,  K=FIN, N=F1
// LAYER 1: A = g_out1 (global),B = W2 (param), C = g_h2,  K=F1,  N=F2
template <int LAYER>
__global__ void __launch_bounds__(256)
k_sgemm(const float* __restrict__ Ain, const float* __restrict__ B) {
    constexpr int K = (LAYER == 0) ? FIN : F1;
    constexpr int N = (LAYER == 0) ? F1  : F2;
    const float* A = (LAYER == 0) ? Ain : g_out1;
    float*       C = (LAYER == 0) ? g_h1 : g_h2;

    const int BM = 128, BN = 128, BK = 8, TM = 8, TN = 8;
    __shared__ __align__(16) float As[BK][BM];
    __shared__ __align__(16) float Bs[BK][BN];
    int tid = threadIdx.x;
    int bx = blockIdx.x, by = blockIdx.y;
    int a_row = tid >> 1;            // 0..127
    int a_col = (tid & 1) * 4;       // 0 or 4
    int b_row = tid >> 5;            // 0..7
    int b_col = (tid & 31) * 4;      // 0..124
    int tr = tid >> 4;               // 0..15
    int tc = tid & 15;               // 0..15

    float acc[TM][TN];
#pragma unroll
    for (int i = 0; i < TM; i++)
#pragma unroll
        for (int j = 0; j < TN; j++) acc[i][j] = 0.f;

    const float* Ap = A + (size_t)(by * BM + a_row) * K + a_col;
    const float* Bp = B + (size_t)b_row * N + bx * BN + b_col;

    for (int k0 = 0; k0 < K; k0 += BK) {
        float4 av = *(const float4*)Ap;
        float4 bv = *(const float4*)Bp;
        Ap += BK;
        Bp += (size_t)BK * N;
        As[a_col + 0][a_row] = av.x;
        As[a_col + 1][a_row] = av.y;
        As[a_col + 2][a_row] = av.z;
        As[a_col + 3][a_row] = av.w;
        *(float4*)&Bs[b_row][b_col] = bv;
        __syncthreads();
#pragma unroll
        for (int k = 0; k < BK; k++) {
            float ar[TM], br[TN];
            float4 t0 = *(const float4*)&As[k][tr * TM];
            float4 t1 = *(const float4*)&As[k][tr * TM + 4];
            ar[0]=t0.x; ar[1]=t0.y; ar[2]=t0.z; ar[3]=t0.w;
            ar[4]=t1.x; ar[5]=t1.y; ar[6]=t1.z; ar[7]=t1.w;
            float4 u0 = *(const float4*)&Bs[k][tc * TN];
            float4 u1 = *(const float4*)&Bs[k][tc * TN + 4];
            br[0]=u0.x; br[1]=u0.y; br[2]=u0.z; br[3]=u0.w;
            br[4]=u1.x; br[5]=u1.y; br[6]=u1.z; br[7]=u1.w;
#pragma unroll
            for (int i = 0; i < TM; i++)
#pragma unroll
                for (int j = 0; j < TN; j++)
                    acc[i][j] = fmaf(ar[i], br[j], acc[i][j]);
        }
        __syncthreads();
    }
#pragma unroll
    for (int i = 0; i < TM; i++) {
        size_t row = (size_t)(by * BM + tr * TM + i);
        float* cp = C + row * N + bx * BN + tc * TN;
        *(float4*)cp       = make_float4(acc[i][0], acc[i][1], acc[i][2], acc[i][3]);
        *(float4*)(cp + 4) = make_float4(acc[i][4], acc[i][5], acc[i][6], acc[i][7]);
    }
}

// ---------------- attention logit precompute -------------------------------
// one warp per (node, head): al_s[n,h] = sum_c h[n,h,c]*a_s[h,c]; same for a_d.
template <int LAYER>
__global__ void k_attn_prep(const float* __restrict__ a_s,
                            const float* __restrict__ a_d) {
    constexpr int C = (LAYER == 0) ? C1 : LATD;
    const float* h   = (LAYER == 0) ? g_h1  : g_h2;
    float*       als = (LAYER == 0) ? g_als1 : g_als2;
    float*       ald = (LAYER == 0) ? g_ald1 : g_ald2;

    int warp = (blockIdx.x * blockDim.x + threadIdx.x) >> 5;
    int lane = threadIdx.x & 31;
    if (warp >= NN * NH) return;
    int n = warp >> 2, hh = warp & 3;
    const float* hp  = h + (size_t)n * NH * C + hh * C;
    const float* asp = a_s + hh * C;
    const float* adp = a_d + hh * C;
    float ss = 0.f, sd = 0.f;
    for (int c = lane; c < C; c += 32) {
        float v = hp[c];
        ss = fmaf(v, asp[c], ss);
        sd = fmaf(v, adp[c], sd);
    }
#pragma unroll
    for (int o = 16; o; o >>= 1) {
        ss += __shfl_xor_sync(0xffffffffu, ss, o);
        sd += __shfl_xor_sync(0xffffffffu, sd, o);
    }
    if (lane == 0) { als[n * NH + hh] = ss; ald[n * NH + hh] = sd; }
}

// ---------------- layer-1 aggregation: warp per (dst, head) ----------------
// out1[d, h*128+c] = relu( (sum_j w_j * h1[src_j, h*128+c]) / denom + b1 )
__global__ void __launch_bounds__(128)
k_aggregate1(const float* __restrict__ b1) {
    int d    = blockIdx.x;
    int head = threadIdx.x >> 5;
    int lane = threadIdx.x & 31;
    int start = g_rowptr[d], end = g_rowptr[d + 1];
    float aldv = g_ald1[d * NH + head];

    float m = -1e30f;
    for (int j = start + lane; j < end; j += 32) {
        int s = g_col[j];
        float e = g_als1[s * NH + head] + aldv;
        e = e > 0.f ? e : 0.2f * e;
        m = fmaxf(m, e);
    }
#pragma unroll
    for (int o = 16; o; o >>= 1) m = fmaxf(m, __shfl_xor_sync(0xffffffffu, m, o));

    float4 acc = make_float4(0.f, 0.f, 0.f, 0.f);
    float denom = 0.f;
    for (int j = start; j < end; j++) {
        int s = g_col[j];
        float e = g_als1[s * NH + head] + aldv;
        e = e > 0.f ? e : 0.2f * e;
        float w = __expf(e - m);
        denom += w;
        const float4* hp = (const float4*)(g_h1 + (size_t)s * F1 + head * C1);
        float4 v = hp[lane];
        acc.x = fmaf(w, v.x, acc.x);
        acc.y = fmaf(w, v.y, acc.y);
        acc.z = fmaf(w, v.z, acc.z);
        acc.w = fmaf(w, v.w, acc.w);
    }
    float inv = 1.f / denom;
    int cbase = head * C1 + lane * 4;
    float4 bb = *(const float4*)(b1 + cbase);
    float4 r;
    r.x = fmaxf(fmaf(acc.x, inv, bb.x), 0.f);
    r.y = fmaxf(fmaf(acc.y, inv, bb.y), 0.f);
    r.z = fmaxf(fmaf(acc.z, inv, bb.z), 0.f);
    r.w = fmaxf(fmaf(acc.w, inv, bb.w), 0.f);
    *(float4*)(g_out1 + (size_t)d * F1 + cbase) = r;
}

// ---------------- layer-2 aggregation: warp per dst, 4 heads fused ---------
// out[d,c] = mean_h( agg_h[c] ) + b2[c]
__global__ void __launch_bounds__(128)
k_aggregate2(const float* __restrict__ b2, float* __restrict__ out) {
    int w = threadIdx.x >> 5;
    int lane = threadIdx.x & 31;
    int d = blockIdx.x * 4 + w;
    int start = g_rowptr[d], end = g_rowptr[d + 1];
    float ald0 = g_ald2[d * 4 + 0];
    float ald1 = g_ald2[d * 4 + 1];
    float ald2v = g_ald2[d * 4 + 2];
    float ald3 = g_ald2[d * 4 + 3];

    float m0 = -1e30f, m1 = -1e30f, m2 = -1e30f, m3 = -1e30f;
    for (int j = start + lane; j < end; j += 32) {
        int s = g_col[j];
        const float* ap = &g_als2[s * 4];
        float e0 = ap[0] + ald0;  e0 = e0 > 0.f ? e0 : 0.2f * e0;  m0 = fmaxf(m0, e0);
        float e1 = ap[1] + ald1;  e1 = e1 > 0.f ? e1 : 0.2f * e1;  m1 = fmaxf(m1, e1);
        float e2 = ap[2] + ald2v; e2 = e2 > 0.f ? e2 : 0.2f * e2;  m2 = fmaxf(m2, e2);
        float e3 = ap[3] + ald3;  e3 = e3 > 0.f ? e3 : 0.2f * e3;  m3 = fmaxf(m3, e3);
    }
#pragma unroll
    for (int o = 16; o; o >>= 1) {
        m0 = fmaxf(m0, __shfl_xor_sync(0xffffffffu, m0, o));
        m1 = fmaxf(m1, __shfl_xor_sync(0xffffffffu, m1, o));
        m2 = fmaxf(m2, __shfl_xor_sync(0xffffffffu, m2, o));
        m3 = fmaxf(m3, __shfl_xor_sync(0xffffffffu, m3, o));
    }
    int hl = lane >> 3;                  // this lane's head
    int coff = (lane & 7) * 8;           // this lane's 8 columns within head
    float mh   = hl == 0 ? m0 : (hl == 1 ? m1 : (hl == 2 ? m2 : m3));
    float aldh = hl == 0 ? ald0 : (hl == 1 ? ald1 : (hl == 2 ? ald2v : ald3));

    float4 accA = make_float4(0.f, 0.f, 0.f, 0.f);
    float4 accB = make_float4(0.f, 0.f, 0.f, 0.f);
    float denom = 0.f;
    for (int j = start; j < end; j++) {
        int s = g_col[j];
        float e = g_als2[s * 4 + hl] + aldh;
        e = e > 0.f ? e : 0.2f * e;
        float wgt = __expf(e - mh);
        denom += wgt;
        const float4* hp = (const float4*)(g_h2 + (size_t)s * F2 + hl * LATD + coff);
        float4 vA = hp[0], vB = hp[1];
        accA.x = fmaf(wgt, vA.x, accA.x);
        accA.y = fmaf(wgt, vA.y, accA.y);
        accA.z = fmaf(wgt, vA.z, accA.z);
        accA.w = fmaf(wgt, vA.w, accA.w);
        accB.x = fmaf(wgt, vB.x, accB.x);
        accB.y = fmaf(wgt, vB.y, accB.y);
        accB.z = fmaf(wgt, vB.z, accB.z);
        accB.w = fmaf(wgt, vB.w, accB.w);
    }
    float inv = 1.f / denom;
    float v[8] = { accA.x * inv, accA.y * inv, accA.z * inv, accA.w * inv,
                   accB.x * inv, accB.y * inv, accB.z * inv, accB.w * inv };
    // sum across the 4 head-lanes holding the same columns (lanes l, l^8, l^16, l^24)
#pragma unroll
    for (int o = 8; o <= 16; o <<= 1)
#pragma unroll
        for (int i = 0; i < 8; i++) v[i] += __shfl_xor_sync(0xffffffffu, v[i], o);

    if (lane < 8) {
        int cb = lane * 8;
#pragma unroll
        for (int i = 0; i < 8; i++)
            out[(size_t)d * LATD + cb + i] = 0.25f * v[i] + b2[cb + i];
    }
}

// ---------------- host launch ----------------------------------------------
extern "C" void kernel_launch(void* const* d_in, const int* in_sizes, int n_in,
                              void* d_out, int out_size) {
    const float* x   = (const float*)d_in[0];
    const void*  ei  = d_in[1];                  // int32 or int64, detected on device
    const float* W1  = (const float*)d_in[2];
    const float* as1 = (const float*)d_in[3];
    const float* ad1 = (const float*)d_in[4];
    const float* b1  = (const float*)d_in[5];
    const float* W2  = (const float*)d_in[6];
    const float* as2 = (const float*)d_in[7];
    const float* ad2 = (const float*)d_in[8];
    const float* b2  = (const float*)d_in[9];
    float*       out = (float*)d_out;

    // CSR build (dst-sorted adjacency with self loops)
    k_detect<<<1, 32>>>(ei);
    k_init_deg<<<NN / 256, 256>>>();
    k_count_deg<<<ERAW / 256, 256>>>(ei);
    k_scan<<<1, 1024>>>();
    k_selfloop<<<NN / 256, 256>>>();
    k_scatter<<<ERAW / 256, 256>>>(ei);

    // Layer 1
    k_sgemm<0><<<dim3(F1 / 128, NN / 128), 256>>>(x, W1);
    k_attn_prep<0><<<(NN * NH) / 8, 256>>>(as1, ad1);
    k_aggregate1<<<NN, 128>>>(b1);

    // Layer 2
    k_sgemm<1><<<dim3(F2 / 128, NN / 128), 256>>>(nullptr, W2);
    k_attn_prep<1><<<(NN * NH) / 8, 256>>>(as2, ad2);
    k_aggregate2<<<NN / 4, 128>>>(b2, out);
}

// round 13
// speedup vs baseline: 1.3105x; 1.3105x over previous
#include <cuda_runtime.h>
#include <cuda_bf16.h>
#include <mma.h>
#include <cstdint>

using namespace nvcuda;

// Problem constants (fixed shapes from reference setup_inputs)
#define NN    16384          // nodes
#define FIN   512            // input features
#define NH    4              // heads
#define C1    128            // layer-1 per-head channels
#define LATD  64             // layer-2 per-head channels
#define ERAW  262144         // raw edges
#define ETOT  (ERAW + NN)    // + self loops = 278528
#define F1    (NH * C1)      // 512
#define F2    (NH * LATD)    // 256
#define KP    1536           // K' = 3*512 (3xBF16 K-tripling)

// ---------------- static scratch (device globals; no runtime alloc) --------
// RULE (R13): __device__ globals are ONLY referenced from device code.
// Never passed as host-side kernel arguments (host shadow address + ATS
// silently swallows the writes).
__device__ __align__(16) float g_h1[(size_t)NN * F1];   // layer-1 projection (32 MB)
__device__ __align__(16) float g_h2[(size_t)NN * F2];   // layer-2 projection (16 MB)
__device__ __align__(16) __nv_bfloat16 g_a1 [(size_t)NN * KP];  // A' layer1 (48 MB)
__device__ __align__(16) __nv_bfloat16 g_a2 [(size_t)NN * KP];  // A' layer2 (48 MB)
__device__ __align__(16) __nv_bfloat16 g_wt1[(size_t)F1 * KP];  // W1'^T [512][1536]
__device__ __align__(16) __nv_bfloat16 g_wt2[(size_t)F2 * KP];  // W2'^T [256][1536]
__device__ float g_als1[NN * NH];
__device__ float g_ald1[NN * NH];
__device__ float g_als2[NN * NH];
__device__ float g_ald2[NN * NH];
__device__ int   g_rowptr[NN + 1];
__device__ int   g_col[ETOT];
__device__ int   g_deg[NN];
__device__ int   g_fill[NN];
__device__ int   g_bsum[128];
__device__ int   g_is64;     // edge_index dtype flag (1 = int64, 0 = int32)

// ---------------- helpers ---------------------------------------------------
__device__ __forceinline__ uint32_t cvta_smem(const void* p) {
    uint32_t a;
    asm("{ .reg .u64 t; cvta.to.shared.u64 t, %1; cvt.u32.u64 %0, t; }"
        : "=r"(a) : "l"(p));
    return a;
}
__device__ __forceinline__ void cpasync16(uint32_t dst, const void* src) {
    asm volatile("cp.async.cg.shared.global [%0], [%1], 16;"
                 :: "r"(dst), "l"(src));
}
#define CP_COMMIT() asm volatile("cp.async.commit_group;" ::: "memory")
#define CP_WAIT(n)  asm volatile("cp.async.wait_group %0;" :: "n"(n) : "memory")

// split v into bf16 hi + residual
__device__ __forceinline__ void bsplit(float v, float& hi, float& lo) {
    hi = __bfloat162float(__float2bfloat16_rn(v));
    lo = v - hi;
}

// ---------------- edge dtype detection -------------------------------------
__global__ void k_detect(const void* __restrict__ ei) {
    if (threadIdx.x == 0 && blockIdx.x == 0) {
        const long long* p = (const long long*)ei;
        int ok = 1;
        for (int i = 0; i < 64; i++) {
            long long v = p[i];
            if (v < 0 || v >= NN) ok = 0;
        }
        g_is64 = ok;
    }
}
__device__ __forceinline__ int edge_at(const void* ei, int idx) {
    if (g_is64) return (int)((const long long*)ei)[idx];
    return ((const int*)ei)[idx];
}

// ---------------- CSR build over dst ---------------------------------------
__global__ void k_init_deg() {
    int i = blockIdx.x * blockDim.x + threadIdx.x;
    if (i < NN) g_deg[i] = 1;                    // self loop
}
__global__ void k_count_deg(const void* __restrict__ ei) {
    int e = blockIdx.x * blockDim.x + threadIdx.x;
    if (e < ERAW) atomicAdd(&g_deg[edge_at(ei, ERAW + e)], 1);
}
// three-phase parallel exclusive scan over 16384 degrees
__global__ void k_scan1() {            // 128 blocks x 128 thr
    __shared__ int sh[128];
    int b = blockIdx.x, t = threadIdx.x;
    int v = g_deg[b * 128 + t];
    sh[t] = v;
    __syncthreads();
    for (int o = 1; o < 128; o <<= 1) {
        int x = (t >= o) ? sh[t - o] : 0;
        __syncthreads();
        sh[t] += x;
        __syncthreads();
    }
    g_rowptr[b * 128 + t] = sh[t] - v;
    if (t == 127) g_bsum[b] = sh[127];
}
__global__ void k_scan2() {            // 1 block x 128 thr
    __shared__ int sh[128];
    int t = threadIdx.x;
    int v = g_bsum[t];
    sh[t] = v;
    __syncthreads();
    for (int o = 1; o < 128; o <<= 1) {
        int x = (t >= o) ? sh[t - o] : 0;
        __syncthreads();
        sh[t] += x;
        __syncthreads();
    }
    g_bsum[t] = sh[t] - v;
}
__global__ void k_scan3() {            // 128 blocks x 128 thr
    int b = blockIdx.x, t = threadIdx.x;
    g_rowptr[b * 128 + t] += g_bsum[b];
    if (b == 0 && t == 0) g_rowptr[NN] = ETOT;
}
__global__ void k_selfloop() {
    int i = blockIdx.x * blockDim.x + threadIdx.x;
    if (i < NN) { g_col[g_rowptr[i]] = i; g_fill[i] = 1; }
}
__global__ void k_scatter(const void* __restrict__ ei) {
    int e = blockIdx.x * blockDim.x + threadIdx.x;
    if (e < ERAW) {
        int d = edge_at(ei, ERAW + e);
        int pos = g_rowptr[d] + atomicAdd(&g_fill[d], 1);
        g_col[pos] = edge_at(ei, e);
    }
}

// ---------------- 3xBF16 K-tripled operand prep -----------------------------
// A' triplet per element: (hi, lo, hi). B' triplet: (hi, hi, lo).
__global__ void k_xsplit3(const float* __restrict__ x) {
    int i = blockIdx.x * blockDim.x + threadIdx.x;     // element index
    float v = x[i];
    float hi, lo;
    bsplit(v, hi, lo);
    __nv_bfloat16 h = __float2bfloat16_rn(hi);
    __nv_bfloat16 l = __float2bfloat16_rn(lo);
    __nv_bfloat16* p = g_a1 + (size_t)i * 3;
    p[0] = h; p[1] = l; p[2] = h;
}

// W [R][Ncols] -> g_wt{1,2} [Ncols][3R] with triplet (hi, hi, lo).
// Destination selected IN DEVICE CODE via template (never a host-passed
// __device__ pointer — that was the R9-R12 bug).
template <int R, int Ncols, int WHICH>
__global__ void k_wsplit3(const float* __restrict__ W) {
    __nv_bfloat16* out = (WHICH == 0) ? g_wt1 : g_wt2;
    __shared__ float tile[32][33];
    int bx = blockIdx.x * 32;   // n base
    int by = blockIdx.y * 32;   // k base
    int tx = threadIdx.x, ty = threadIdx.y;
    for (int i = ty; i < 32; i += 8)
        tile[i][tx] = W[(size_t)(by + i) * Ncols + bx + tx];
    __syncthreads();
    for (int i = ty; i < 32; i += 8) {
        float v = tile[tx][i];           // W[by+tx][bx+i]
        int n = bx + i, k = by + tx;
        float hi, lo;
        bsplit(v, hi, lo);
        __nv_bfloat16 h = __float2bfloat16_rn(hi);
        __nv_bfloat16 l = __float2bfloat16_rn(lo);
        __nv_bfloat16* p = out + (size_t)n * (3 * R) + 3 * k;
        p[0] = h; p[1] = h; p[2] = l;
    }
}

// ---------------- wmma bf16 GEMM --------------------------------------------
// C[M,NCOLS] = A'[M,1536] x B'^T[NCOLS,1536] (fp32 accum).
// 128x128 tile, BK=32, STATIC smem (<=48KB, no opt-in needed), 2-stage
// double buffer, 8 warps (4 over M x 2 over N), each warp 32x64 via
// 2x4 wmma 16x16x16 fragments.
#define BK2   32
#define NCHK2 (KP / BK2)                 // 48
#define LDA2  40                         // padded row stride in elements

template <int LAYER>
__global__ void __launch_bounds__(256) k_wgemm() {
    constexpr int NCOLS = (LAYER == 0) ? F1 : F2;
    const __nv_bfloat16* A = (LAYER == 0) ? g_a1 : g_a2;
    const __nv_bfloat16* B = (LAYER == 0) ? g_wt1 : g_wt2;
    float*               C = (LAYER == 0) ? g_h1 : g_h2;

    __shared__ __align__(16) __nv_bfloat16 sA[2][128 * LDA2];  // 2x10240 B
    __shared__ __align__(16) __nv_bfloat16 sB[2][128 * LDA2];  // 2x10240 B

    int tid  = threadIdx.x;
    int warp = tid >> 5;
    int tm = blockIdx.y, tn = blockIdx.x;
    int warpM = (warp & 3) * 32;        // 4 warps over M
    int warpN = (warp >> 2) * 64;       // 2 warps over N

    // cp.async: 128 rows x 64B per tile per chunk; 2 threads/row x 32B each
    int row  = tid >> 1;
    int half = (tid & 1) * 32;           // byte offset in row (0 or 32)
    const char* aSrc = (const char*)(A + (size_t)(tm * 128 + row) * KP) + half;
    const char* bSrc = (const char*)(B + (size_t)(tn * 128 + row) * KP) + half;
    uint32_t dA[2], dB[2];
#pragma unroll
    for (int s = 0; s < 2; s++) {
        dA[s] = cvta_smem(&sA[s][0]) + (uint32_t)row * (LDA2 * 2) + half;
        dB[s] = cvta_smem(&sB[s][0]) + (uint32_t)row * (LDA2 * 2) + half;
    }

    wmma::fragment<wmma::accumulator, 16, 16, 16, float> c[2][4];
#pragma unroll
    for (int mi = 0; mi < 2; mi++)
#pragma unroll
        for (int ni = 0; ni < 4; ni++)
            wmma::fill_fragment(c[mi][ni], 0.f);

    // preload chunk 0 into stage 0
    cpasync16(dA[0], aSrc);
    cpasync16(dA[0] + 16, aSrc + 16);
    cpasync16(dB[0], bSrc);
    cpasync16(dB[0] + 16, bSrc + 16);
    CP_COMMIT();

    for (int kt = 0; kt < NCHK2; kt++) {
        int buf = kt & 1;
        if (kt + 1 < NCHK2) {
            int nb = (kt + 1) & 1;
            const char* as2 = aSrc + (size_t)(kt + 1) * 64;
            const char* bs2 = bSrc + (size_t)(kt + 1) * 64;
            cpasync16(dA[nb], as2);
            cpasync16(dA[nb] + 16, as2 + 16);
            cpasync16(dB[nb], bs2);
            cpasync16(dB[nb] + 16, bs2 + 16);
            CP_COMMIT();
            CP_WAIT(1);
        } else {
            CP_WAIT(0);
        }
        __syncthreads();

#pragma unroll
        for (int ks = 0; ks < 2; ks++) {
            wmma::fragment<wmma::matrix_a, 16, 16, 16, __nv_bfloat16, wmma::row_major> af[2];
#pragma unroll
            for (int mi = 0; mi < 2; mi++)
                wmma::load_matrix_sync(af[mi],
                    &sA[buf][(warpM + mi * 16) * LDA2 + ks * 16], LDA2);
            wmma::fragment<wmma::matrix_b, 16, 16, 16, __nv_bfloat16, wmma::col_major> bf[4];
#pragma unroll
            for (int ni = 0; ni < 4; ni++)
                wmma::load_matrix_sync(bf[ni],
                    &sB[buf][(warpN + ni * 16) * LDA2 + ks * 16], LDA2);
#pragma unroll
            for (int mi = 0; mi < 2; mi++)
#pragma unroll
                for (int ni = 0; ni < 4; ni++)
                    wmma::mma_sync(c[mi][ni], af[mi], bf[ni], c[mi][ni]);
        }
        __syncthreads();   // protect buf from next iteration's prefetch
    }

    // epilogue
#pragma unroll
    for (int mi = 0; mi < 2; mi++) {
        int r0 = tm * 128 + warpM + mi * 16;
#pragma unroll
        for (int ni = 0; ni < 4; ni++) {
            int c0 = tn * 128 + warpN + ni * 16;
            wmma::store_matrix_sync(C + (size_t)r0 * NCOLS + c0,
                                    c[mi][ni], NCOLS, wmma::mem_row_major);
        }
    }
}

// ---------------- attention logit precompute -------------------------------
template <int LAYER>
__global__ void k_attn_prep(const float* __restrict__ a_s,
                            const float* __restrict__ a_d) {
    constexpr int C = (LAYER == 0) ? C1 : LATD;
    const float* h   = (LAYER == 0) ? g_h1  : g_h2;
    float*       als = (LAYER == 0) ? g_als1 : g_als2;
    float*       ald = (LAYER == 0) ? g_ald1 : g_ald2;

    int warp = (blockIdx.x * blockDim.x + threadIdx.x) >> 5;
    int lane = threadIdx.x & 31;
    if (warp >= NN * NH) return;
    int n = warp >> 2, hh = warp & 3;
    const float* hp  = h + (size_t)n * NH * C + hh * C;
    const float* asp = a_s + hh * C;
    const float* adp = a_d + hh * C;
    float ss = 0.f, sd = 0.f;
    for (int c = lane; c < C; c += 32) {
        float v = hp[c];
        ss = fmaf(v, asp[c], ss);
        sd = fmaf(v, adp[c], sd);
    }
#pragma unroll
    for (int o = 16; o; o >>= 1) {
        ss += __shfl_xor_sync(0xffffffffu, ss, o);
        sd += __shfl_xor_sync(0xffffffffu, sd, o);
    }
    if (lane == 0) { als[n * NH + hh] = ss; ald[n * NH + hh] = sd; }
}

// ---------------- layer-1 aggregation: warp per (dst, head) ----------------
// writes relu(agg + b1) directly as K-tripled bf16 A' for GEMM2 (scalar stores)
__global__ void __launch_bounds__(128)
k_aggregate1(const float* __restrict__ b1) {
    int d    = blockIdx.x;
    int head = threadIdx.x >> 5;
    int lane = threadIdx.x & 31;
    int start = g_rowptr[d], end = g_rowptr[d + 1];
    float aldv = g_ald1[d * NH + head];

    float m = -1e30f;
    for (int j = start + lane; j < end; j += 32) {
        int s = g_col[j];
        float e = g_als1[s * NH + head] + aldv;
        e = e > 0.f ? e : 0.2f * e;
        m = fmaxf(m, e);
    }
#pragma unroll
    for (int o = 16; o; o >>= 1) m = fmaxf(m, __shfl_xor_sync(0xffffffffu, m, o));

    float4 acc = make_float4(0.f, 0.f, 0.f, 0.f);
    float denom = 0.f;
    for (int j = start; j < end; j++) {
        int s = g_col[j];
        float e = g_als1[s * NH + head] + aldv;
        e = e > 0.f ? e : 0.2f * e;
        float w = __expf(e - m);
        denom += w;
        const float4* hp = (const float4*)(g_h1 + (size_t)s * F1 + head * C1);
        float4 v = hp[lane];
        acc.x = fmaf(w, v.x, acc.x);
        acc.y = fmaf(w, v.y, acc.y);
        acc.z = fmaf(w, v.z, acc.z);
        acc.w = fmaf(w, v.w, acc.w);
    }
    float inv = 1.f / denom;
    int cbase = head * C1 + lane * 4;
    float4 bb = *(const float4*)(b1 + cbase);
    float r[4];
    r[0] = fmaxf(fmaf(acc.x, inv, bb.x), 0.f);
    r[1] = fmaxf(fmaf(acc.y, inv, bb.y), 0.f);
    r[2] = fmaxf(fmaf(acc.z, inv, bb.z), 0.f);
    r[3] = fmaxf(fmaf(acc.w, inv, bb.w), 0.f);
    __nv_bfloat16* o = g_a2 + (size_t)d * KP + 3 * cbase;
#pragma unroll
    for (int j = 0; j < 4; j++) {
        float hi, lo;
        bsplit(r[j], hi, lo);
        __nv_bfloat16 h = __float2bfloat16_rn(hi);
        __nv_bfloat16 l = __float2bfloat16_rn(lo);
        o[3 * j + 0] = h; o[3 * j + 1] = l; o[3 * j + 2] = h;
    }
}

// ---------------- layer-2 aggregation: warp per dst, 4 heads fused ---------
__global__ void __launch_bounds__(128)
k_aggregate2(const float* __restrict__ b2, float* __restrict__ out) {
    int w = threadIdx.x >> 5;
    int lane = threadIdx.x & 31;
    int d = blockIdx.x * 4 + w;
    int start = g_rowptr[d], end = g_rowptr[d + 1];
    float ald0 = g_ald2[d * 4 + 0];
    float ald1 = g_ald2[d * 4 + 1];
    float ald2v = g_ald2[d * 4 + 2];
    float ald3 = g_ald2[d * 4 + 3];

    float m0 = -1e30f, m1 = -1e30f, m2 = -1e30f, m3 = -1e30f;
    for (int j = start + lane; j < end; j += 32) {
        int s = g_col[j];
        const float* ap = &g_als2[s * 4];
        float e0 = ap[0] + ald0;  e0 = e0 > 0.f ? e0 : 0.2f * e0;  m0 = fmaxf(m0, e0);
        float e1 = ap[1] + ald1;  e1 = e1 > 0.f ? e1 : 0.2f * e1;  m1 = fmaxf(m1, e1);
        float e2 = ap[2] + ald2v; e2 = e2 > 0.f ? e2 : 0.2f * e2;  m2 = fmaxf(m2, e2);
        float e3 = ap[3] + ald3;  e3 = e3 > 0.f ? e3 : 0.2f * e3;  m3 = fmaxf(m3, e3);
    }
#pragma unroll
    for (int o = 16; o; o >>= 1) {
        m0 = fmaxf(m0, __shfl_xor_sync(0xffffffffu, m0, o));
        m1 = fmaxf(m1, __shfl_xor_sync(0xffffffffu, m1, o));
        m2 = fmaxf(m2, __shfl_xor_sync(0xffffffffu, m2, o));
        m3 = fmaxf(m3, __shfl_xor_sync(0xffffffffu, m3, o));
    }
    int hl = lane >> 3;
    int coff = (lane & 7) * 8;
    float mh   = hl == 0 ? m0 : (hl == 1 ? m1 : (hl == 2 ? m2 : m3));
    float aldh = hl == 0 ? ald0 : (hl == 1 ? ald1 : (hl == 2 ? ald2v : ald3));

    float4 accA = make_float4(0.f, 0.f, 0.f, 0.f);
    float4 accB = make_float4(0.f, 0.f, 0.f, 0.f);
    float denom = 0.f;
    for (int j = start; j < end; j++) {
        int s = g_col[j];
        float e = g_als2[s * 4 + hl] + aldh;
        e = e > 0.f ? e : 0.2f * e;
        float wgt = __expf(e - mh);
        denom += wgt;
        const float4* hp = (const float4*)(g_h2 + (size_t)s * F2 + hl * LATD + coff);
        float4 vA = hp[0], vB = hp[1];
        accA.x = fmaf(wgt, vA.x, accA.x);
        accA.y = fmaf(wgt, vA.y, accA.y);
        accA.z = fmaf(wgt, vA.z, accA.z);
        accA.w = fmaf(wgt, vA.w, accA.w);
        accB.x = fmaf(wgt, vB.x, accB.x);
        accB.y = fmaf(wgt, vB.y, accB.y);
        accB.z = fmaf(wgt, vB.z, accB.z);
        accB.w = fmaf(wgt, vB.w, accB.w);
    }
    float inv = 1.f / denom;
    float v[8] = { accA.x * inv, accA.y * inv, accA.z * inv, accA.w * inv,
                   accB.x * inv, accB.y * inv, accB.z * inv, accB.w * inv };
#pragma unroll
    for (int o = 8; o <= 16; o <<= 1)
#pragma unroll
        for (int i = 0; i < 8; i++) v[i] += __shfl_xor_sync(0xffffffffu, v[i], o);

    if (lane < 8) {
        int cb = lane * 8;
#pragma unroll
        for (int i = 0; i < 8; i++)
            out[(size_t)d * LATD + cb + i] = 0.25f * v[i] + b2[cb + i];
    }
}

// ---------------- host launch ----------------------------------------------
extern "C" void kernel_launch(void* const* d_in, const int* in_sizes, int n_in,
                              void* d_out, int out_size) {
    const float* x   = (const float*)d_in[0];
    const void*  ei  = d_in[1];                  // int32 or int64, detected on device
    const float* W1  = (const float*)d_in[2];
    const float* as1 = (const float*)d_in[3];
    const float* ad1 = (const float*)d_in[4];
    const float* b1  = (const float*)d_in[5];
    const float* W2  = (const float*)d_in[6];
    const float* as2 = (const float*)d_in[7];
    const float* ad2 = (const float*)d_in[8];
    const float* b2  = (const float*)d_in[9];
    float*       out = (float*)d_out;

    // operand prep (bf16 K-tripled splits + W transposes) — destinations
    // selected in device code, never passed from host.
    k_xsplit3<<<(NN * FIN) / 256, 256>>>(x);
    k_wsplit3<FIN, F1, 0><<<dim3(F1 / 32, FIN / 32), dim3(32, 8)>>>(W1);
    k_wsplit3<F1, F2, 1><<<dim3(F2 / 32, F1 / 32), dim3(32, 8)>>>(W2);

    // CSR build (dst-sorted adjacency with self loops)
    k_detect<<<1, 32>>>(ei);
    k_init_deg<<<NN / 256, 256>>>();
    k_count_deg<<<ERAW / 256, 256>>>(ei);
    k_scan1<<<128, 128>>>();
    k_scan2<<<1, 128>>>();
    k_scan3<<<128, 128>>>();
    k_selfloop<<<NN / 256, 256>>>();
    k_scatter<<<ERAW / 256, 256>>>(ei);

    // Layer 1
    k_wgemm<0><<<dim3(F1 / 128, NN / 128), 256>>>();
    k_attn_prep<0><<<(NN * NH) / 8, 256>>>(as1, ad1);
    k_aggregate1<<<NN, 128>>>(b1);

    // Layer 2
    k_wgemm<1><<<dim3(F2 / 128, NN / 128), 256>>>();
    k_attn_prep<1><<<(NN * NH) / 8, 256>>>(as2, ad2);
    k_aggregate2<<<NN / 4, 128>>>(b2, out);
}